// round 5
// baseline (speedup 1.0000x reference)
#include <cuda_runtime.h>
#include <cuda_fp16.h>
#include <cstdint>

// GraphSAGE layer, N=8192, D_IN=D_OUT=512 — mma.sync fp16, fused-degree agg.
// out = relu( x @ (W_self@Wc_top) + agg @ (W_nb@Wc_bot) + c )
// agg = (mask @ x) * invdeg, mask = (adj > 0) converted on the fly from adj.
// Degrees are computed INSIDE the agg GEMM (every CTA sees its full rows).
// Precision: fp16 single-pass agg; final = (Yh+Yl) @ Wf (Y hi/lo fp16 split).

#define NN 8192
#define DD 512

// ------------------------------- device globals (no allocations allowed) ----
__device__ __align__(256) __half g_xh[(size_t)NN * DD];     // x fp16 (agg B)
__device__ __align__(256) __half g_Yh[(size_t)NN * 1024];   // [x|agg] hi
__device__ __align__(256) __half g_Yl[(size_t)NN * 1024];   // [x|agg] lo
__device__ __align__(256) __half g_Wf[(size_t)1024 * DD];   // fused W fp16
__device__ float g_c[DD];

// ------------------------------------------------------------ PTX helpers ---
__device__ __forceinline__ uint32_t smem_u32(const void* p) {
    uint32_t a;
    asm("{ .reg .u64 t; cvta.to.shared.u64 t, %1; cvt.u32.u64 %0, t; }"
        : "=r"(a) : "l"(p));
    return a;
}
#define CP16(dst, src) \
    asm volatile("cp.async.cg.shared.global [%0], [%1], 16;" \
                 :: "r"(dst), "l"(src) : "memory")
#define CP_COMMIT() asm volatile("cp.async.commit_group;" ::: "memory")
#define CP_WAIT1() asm volatile("cp.async.wait_group 1;" ::: "memory")
#define CP_WAIT0() asm volatile("cp.async.wait_group 0;" ::: "memory")

__device__ __forceinline__ void ldsm4(uint32_t* r, uint32_t addr) {
    asm volatile("ldmatrix.sync.aligned.m8n8.x4.shared.b16 {%0,%1,%2,%3}, [%4];"
                 : "=r"(r[0]), "=r"(r[1]), "=r"(r[2]), "=r"(r[3]) : "r"(addr));
}
__device__ __forceinline__ void ldsm4t(uint32_t* r, uint32_t addr) {
    asm volatile("ldmatrix.sync.aligned.m8n8.x4.trans.shared.b16 {%0,%1,%2,%3}, [%4];"
                 : "=r"(r[0]), "=r"(r[1]), "=r"(r[2]), "=r"(r[3]) : "r"(addr));
}
__device__ __forceinline__ void mma_f16(float* d, const uint32_t* a,
                                        const uint32_t* b) {
    asm volatile(
        "mma.sync.aligned.m16n8k16.row.col.f32.f16.f16.f32 "
        "{%0,%1,%2,%3}, {%4,%5,%6,%7}, {%8,%9}, {%0,%1,%2,%3};"
        : "+f"(d[0]), "+f"(d[1]), "+f"(d[2]), "+f"(d[3])
        : "r"(a[0]), "r"(a[1]), "r"(a[2]), "r"(a[3]), "r"(b[0]), "r"(b[1]));
}

// ------------------- x -> xh (node-major) + Yh/Yl cols 0..511 ---------------
__global__ void conv_x_kernel(const float* __restrict__ x) {
    int idx = blockIdx.x * 256 + threadIdx.x;     // over N*D/4 float4
    float4 v = ((const float4*)x)[idx];
    float f[4] = {v.x, v.y, v.z, v.w};
    __half h[4], l[4];
#pragma unroll
    for (int j = 0; j < 4; j++) {
        h[j] = __float2half(f[j]);
        l[j] = __float2half(f[j] - __half2float(h[j]));
    }
    __half2 h01, h23, l01, l23;
    h01.x = h[0]; h01.y = h[1]; h23.x = h[2]; h23.y = h[3];
    l01.x = l[0]; l01.y = l[1]; l23.x = l[2]; l23.y = l[3];
    size_t o = (size_t)idx * 4;
    *(__half2*)&g_xh[o] = h01; *(__half2*)&g_xh[o + 2] = h23;
    int r = idx >> 7, c = (idx & 127) * 4;
    size_t oy = (size_t)r * 1024 + c;
    *(__half2*)&g_Yh[oy] = h01; *(__half2*)&g_Yh[oy + 2] = h23;
    *(__half2*)&g_Yl[oy] = l01; *(__half2*)&g_Yl[oy + 2] = l23;
}

// ---------- small 512^3 GEMMs (both halves, grid.z) -> Wf fp16 --------------
__global__ void small_gemm512(const float* __restrict__ W_self,
                              const float* __restrict__ W_nb,
                              const float* __restrict__ W_comb) {
    const int half = blockIdx.z;
    const float* A = half ? W_nb : W_self;
    const float* B = W_comb + (size_t)half * 512 * 512;
    __shared__ float As[16][68];
    __shared__ float Bs[16][64];
    const int t = threadIdx.x;
    const int bm = blockIdx.y * 64, bn = blockIdx.x * 64;
    const int ty = t >> 4, tx = t & 15;
    float acc[4][4] = {};
    for (int k0 = 0; k0 < 512; k0 += 16) {
        {
            int row = t >> 2, c4 = t & 3;
            float4 v = *(const float4*)(A + (size_t)(bm + row) * 512 + k0 + c4 * 4);
            As[c4 * 4 + 0][row] = v.x;
            As[c4 * 4 + 1][row] = v.y;
            As[c4 * 4 + 2][row] = v.z;
            As[c4 * 4 + 3][row] = v.w;
        }
        {
            int kr = t >> 4, c4 = t & 15;
            *(float4*)&Bs[kr][c4 * 4] =
                *(const float4*)(B + (size_t)(k0 + kr) * 512 + bn + c4 * 4);
        }
        __syncthreads();
#pragma unroll
        for (int k = 0; k < 16; k++) {
            float4 av = *(const float4*)&As[k][ty * 4];
            float4 bv = *(const float4*)&Bs[k][tx * 4];
            float a[4] = {av.x, av.y, av.z, av.w};
            float b[4] = {bv.x, bv.y, bv.z, bv.w};
#pragma unroll
            for (int i = 0; i < 4; i++)
#pragma unroll
                for (int j = 0; j < 4; j++) acc[i][j] += a[i] * b[j];
        }
        __syncthreads();
    }
#pragma unroll
    for (int i = 0; i < 4; i++)
#pragma unroll
        for (int j = 0; j < 4; j++) {
            int kk = half * 512 + bm + ty * 4 + i;   // K index of final GEMM
            int n = bn + tx * 4 + j;
            g_Wf[(size_t)kk * 512 + n] = __float2half(acc[i][j]);
        }
}

// ----------------------------------------------------------- fused bias -----
__global__ void bias_kernel(const float* __restrict__ b_self,
                            const float* __restrict__ b_nb,
                            const float* __restrict__ b_comb,
                            const float* __restrict__ Wc) {
    const int n = blockIdx.x;
    float s = 0.0f;
    for (int o = threadIdx.x; o < 1024; o += 256) {
        float b = (o < 512) ? b_self[o] : b_nb[o - 512];
        s += b * Wc[(size_t)o * 512 + n];
    }
    __shared__ float red[256];
    red[threadIdx.x] = s;
    __syncthreads();
    for (int o = 128; o > 0; o >>= 1) {
        if (threadIdx.x < o) red[threadIdx.x] += red[threadIdx.x + o];
        __syncthreads();
    }
    if (threadIdx.x == 0) g_c[n] = red[0] + b_comb[n];
}

// ----------------------------------------- agg GEMM: adj direct + fused deg -
// BM=128, BN=128, BK=32; 8 warps (2m x 4n), warp tile 64x32, K=8192.
// A loaded from adj via LDG int4 -> fp16 0/1 (prefetch regs, double buffer);
// per-row neighbor counts accumulated alongside; epilogue *invdeg ->
// Yh/Yl cols 512..1023 (fp16 hi/lo split).
#define SA_T (128 * 40)   // elems per A tile (rows padded to 40 = 80 B)
#define SB_T (32 * 136)   // elems per B tile (rows padded to 136 = 272 B)
#define AGG_SMEM ((2 * SA_T + 2 * SB_T) * 2 + 512)
#define FIN_SMEM ((4 * SA_T + 2 * SB_T) * 2)

__device__ __forceinline__ void ldg_A(int4* ar, const int* __restrict__ adj,
                                      int bm, int k0, int tid) {
#pragma unroll
    for (int j = 0; j < 4; j++) {
        int i = tid + j * 256;
        int row = i >> 3, q = i & 7;
        ar[j] = *(const int4*)(adj + (size_t)(bm + row) * NN + k0 + q * 4);
    }
}
__device__ __forceinline__ void sts_count_A(const int4* ar, uint32_t sb,
                                            int buf, int tid, int* cnt) {
#pragma unroll
    for (int j = 0; j < 4; j++) {
        int i = tid + j * 256;
        int row = i >> 3, q = i & 7;
        int4 v = ar[j];
        uint32_t u0 = (v.x > 0 ? 0x3C00u : 0u) | (v.y > 0 ? 0x3C000000u : 0u);
        uint32_t u1 = (v.z > 0 ? 0x3C00u : 0u) | (v.w > 0 ? 0x3C000000u : 0u);
        cnt[j] += (v.x > 0) + (v.y > 0) + (v.z > 0) + (v.w > 0);
        uint32_t dst = sb + (buf * SA_T + row * 40 + q * 4) * 2;
        asm volatile("st.shared.v2.b32 [%0], {%1,%2};"
                     :: "r"(dst), "r"(u0), "r"(u1) : "memory");
    }
}

__global__ void __launch_bounds__(256, 2) agg_gemm(const int* __restrict__ adj) {
    constexpr int NCH = 256;                       // K = 8192 / 32
    constexpr int BOFF = 2 * SA_T;
    extern __shared__ __half sm[];
    const uint32_t sb = smem_u32(sm);
    float* sdeg = (float*)(sm + 2 * SA_T + 2 * SB_T);
    const int tid = threadIdx.x, lane = tid & 31, wid = tid >> 5;
    const int wm = wid & 1, wn = wid >> 1;
    const int bm = blockIdx.y * 128, bn = blockIdx.x * 128;

    float acc[4][4][4] = {};
    int cnt[4] = {0, 0, 0, 0};
    int4 ar[4];

    // prologue: chunk 0
    ldg_A(ar, adj, bm, 0, tid);
#pragma unroll
    for (int j = 0; j < 2; j++) {                  // B chunk 0
        int idx = tid + j * 256;
        int row = idx >> 4, q = idx & 15;
        CP16(sb + (BOFF + row * 136 + q * 8) * 2,
             g_xh + (size_t)row * DD + bn + q * 8);
    }
    CP_COMMIT();
    sts_count_A(ar, sb, 0, tid, cnt);

    for (int c = 0; c < NCH; ++c) {
        const int buf = c & 1;
        if (c + 1 < NCH) {
            ldg_A(ar, adj, bm, (c + 1) * 32, tid); // long-latency, consumed late
#pragma unroll
            for (int j = 0; j < 2; j++) {
                int idx = tid + j * 256;
                int row = idx >> 4, q = idx & 15;
                CP16(sb + (BOFF + (buf ^ 1) * SB_T + row * 136 + q * 8) * 2,
                     g_xh + (size_t)((c + 1) * 32 + row) * DD + bn + q * 8);
            }
            CP_COMMIT();
            CP_WAIT1();
        } else {
            CP_WAIT0();
        }
        __syncthreads();

#pragma unroll
        for (int ks = 0; ks < 2; ks++) {
            uint32_t Af[4][4];
            uint32_t Bf[4][2];
#pragma unroll
            for (int i = 0; i < 4; i++) {
                int row = wm * 64 + i * 16 + (lane & 15);
                int col = ks * 16 + ((lane >> 4) << 3);
                ldsm4(Af[i], sb + (buf * SA_T + row * 40 + col) * 2);
            }
#pragma unroll
            for (int jp = 0; jp < 2; jp++) {
                int row = ks * 16 + (lane & 15);
                int col = wn * 32 + jp * 16 + ((lane >> 4) << 3);
                uint32_t r[4];
                ldsm4t(r, sb + (BOFF + buf * SB_T + row * 136 + col) * 2);
                Bf[jp * 2][0] = r[0];     Bf[jp * 2][1] = r[1];
                Bf[jp * 2 + 1][0] = r[2]; Bf[jp * 2 + 1][1] = r[3];
            }
#pragma unroll
            for (int i = 0; i < 4; i++)
#pragma unroll
                for (int jn = 0; jn < 4; jn++)
                    mma_f16(acc[i][jn], Af[i], Bf[jn]);
        }
        if (c + 1 < NCH) sts_count_A(ar, sb, buf ^ 1, tid, cnt);
        __syncthreads();
    }

    // ----- degree reduction: 8 consecutive lanes hold one row's partials ----
#pragma unroll
    for (int d = 1; d < 8; d <<= 1)
#pragma unroll
        for (int j = 0; j < 4; j++)
            cnt[j] += __shfl_xor_sync(0xFFFFFFFFu, cnt[j], d);
    if ((tid & 7) == 0) {
#pragma unroll
        for (int j = 0; j < 4; j++)
            sdeg[(tid >> 3) + 32 * j] = 1.0f / fmaxf((float)cnt[j], 1.0f);
    }
    __syncthreads();

    // --------------------------------------------------------- epilogue ----
    const int gid = lane >> 2, tig = lane & 3;
#pragma unroll
    for (int i = 0; i < 4; i++)
#pragma unroll
        for (int h = 0; h < 2; h++) {
            const int lr = wm * 64 + i * 16 + gid + h * 8;
            const int gr = bm + lr;
            const float s = sdeg[lr];
#pragma unroll
            for (int jn = 0; jn < 4; jn++) {
                int col = bn + wn * 32 + jn * 8 + tig * 2;
                float v0 = acc[i][jn][h * 2 + 0] * s;
                float v1 = acc[i][jn][h * 2 + 1] * s;
                __half h0 = __float2half(v0);
                __half h1 = __float2half(v1);
                __half2 hp, lp;
                hp.x = h0; hp.y = h1;
                lp.x = __float2half(v0 - __half2float(h0));
                lp.y = __float2half(v1 - __half2float(h1));
                *(__half2*)&g_Yh[(size_t)gr * 1024 + 512 + col] = hp;
                *(__half2*)&g_Yl[(size_t)gr * 1024 + 512 + col] = lp;
            }
        }
}

// ------------------------------- final GEMM: (Yh+Yl) @ Wf, +bias, relu ------
__global__ void __launch_bounds__(256, 2) fin_gemm(float* __restrict__ outp) {
    constexpr int NCH = 32;                        // K = 1024 / 32
    constexpr int BOFF = 4 * SA_T;
    extern __shared__ __half sm[];
    const uint32_t sb = smem_u32(sm);
    const int tid = threadIdx.x, lane = tid & 31, wid = tid >> 5;
    const int wm = wid & 1, wn = wid >> 1;
    const int bm = blockIdx.y * 128, bn = blockIdx.x * 128;
    const __half* Ap[2] = {g_Yh, g_Yl};

    float acc[4][4][4] = {};

    auto fill = [&](int k0, int buf) {
#pragma unroll
        for (int a = 0; a < 2; a++)
#pragma unroll
            for (int j = 0; j < 2; j++) {
                int idx = tid + j * 256;
                int row = idx >> 2, q = idx & 3;
                CP16(sb + ((buf * 2 + a) * SA_T + row * 40 + q * 8) * 2,
                     Ap[a] + (size_t)(bm + row) * 1024 + k0 + q * 8);
            }
#pragma unroll
        for (int j = 0; j < 2; j++) {
            int idx = tid + j * 256;
            int row = idx >> 4, q = idx & 15;
            CP16(sb + (BOFF + buf * SB_T + row * 136 + q * 8) * 2,
                 g_Wf + (size_t)(k0 + row) * DD + bn + q * 8);
        }
    };

    fill(0, 0);
    CP_COMMIT();
    for (int c = 0; c < NCH; ++c) {
        const int buf = c & 1;
        if (c + 1 < NCH) { fill((c + 1) * 32, buf ^ 1); CP_COMMIT(); CP_WAIT1(); }
        else CP_WAIT0();
        __syncthreads();
#pragma unroll
        for (int ks = 0; ks < 2; ks++) {
            uint32_t Af[2][4][4];
            uint32_t Bf[4][2];
#pragma unroll
            for (int a = 0; a < 2; a++)
#pragma unroll
                for (int i = 0; i < 4; i++) {
                    int row = wm * 64 + i * 16 + (lane & 15);
                    int col = ks * 16 + ((lane >> 4) << 3);
                    ldsm4(Af[a][i],
                          sb + ((buf * 2 + a) * SA_T + row * 40 + col) * 2);
                }
#pragma unroll
            for (int jp = 0; jp < 2; jp++) {
                int row = ks * 16 + (lane & 15);
                int col = wn * 32 + jp * 16 + ((lane >> 4) << 3);
                uint32_t r[4];
                ldsm4t(r, sb + (BOFF + buf * SB_T + row * 136 + col) * 2);
                Bf[jp * 2][0] = r[0];     Bf[jp * 2][1] = r[1];
                Bf[jp * 2 + 1][0] = r[2]; Bf[jp * 2 + 1][1] = r[3];
            }
#pragma unroll
            for (int a = 0; a < 2; a++)
#pragma unroll
                for (int i = 0; i < 4; i++)
#pragma unroll
                    for (int jn = 0; jn < 4; jn++)
                        mma_f16(acc[i][jn], Af[a][i], Bf[jn]);
        }
        __syncthreads();
    }

    const int gid = lane >> 2, tig = lane & 3;
#pragma unroll
    for (int i = 0; i < 4; i++)
#pragma unroll
        for (int h = 0; h < 2; h++) {
            const int gr = bm + wm * 64 + i * 16 + gid + h * 8;
#pragma unroll
            for (int jn = 0; jn < 4; jn++) {
                int col = bn + wn * 32 + jn * 8 + tig * 2;
                float2 o;
                o.x = fmaxf(acc[i][jn][h * 2 + 0] + g_c[col], 0.0f);
                o.y = fmaxf(acc[i][jn][h * 2 + 1] + g_c[col + 1], 0.0f);
                *(float2*)&outp[(size_t)gr * 512 + col] = o;
            }
        }
}

// ---------------------------------------------------------------- launch ----
extern "C" void kernel_launch(void* const* d_in, const int* in_sizes, int n_in,
                              void* d_out, int out_size) {
    const float* x      = (const float*)d_in[0];
    const int*   adj    = (const int*)d_in[1];
    const float* W_self = (const float*)d_in[2];
    const float* b_self = (const float*)d_in[3];
    const float* W_nb   = (const float*)d_in[4];
    const float* b_nb   = (const float*)d_in[5];
    const float* W_comb = (const float*)d_in[6];
    const float* b_comb = (const float*)d_in[7];
    float* out = (float*)d_out;

    static cudaStream_t s2 = 0;
    static cudaEvent_t evR = 0, evS = 0;
    static int inited = 0;
    if (!inited) {
        inited = 1;
        cudaFuncSetAttribute(agg_gemm,
                             cudaFuncAttributeMaxDynamicSharedMemorySize, AGG_SMEM);
        cudaFuncSetAttribute(fin_gemm,
                             cudaFuncAttributeMaxDynamicSharedMemorySize, FIN_SMEM);
        if (cudaStreamCreateWithFlags(&s2, cudaStreamNonBlocking) != cudaSuccess)
            s2 = 0;
        if (s2 &&
            (cudaEventCreateWithFlags(&evR, cudaEventDisableTiming) != cudaSuccess ||
             cudaEventCreateWithFlags(&evS, cudaEventDisableTiming) != cudaSuccess))
            s2 = 0;
    }

    if (s2) {
        // fork: weight-fusion chain runs concurrently with conv+agg
        cudaEventRecord(evR, 0);
        cudaStreamWaitEvent(s2, evR, 0);
        small_gemm512<<<dim3(8, 8, 2), 256, 0, s2>>>(W_self, W_nb, W_comb);
        bias_kernel<<<512, 256, 0, s2>>>(b_self, b_nb, b_comb, W_comb);
        cudaEventRecord(evS, s2);

        conv_x_kernel<<<NN * DD / 4 / 256, 256>>>(x);
        agg_gemm<<<dim3(4, 64), 256, AGG_SMEM>>>(adj);

        cudaStreamWaitEvent(0, evS, 0);            // join before final
        fin_gemm<<<dim3(4, 64), 256, FIN_SMEM>>>(out);
    } else {
        conv_x_kernel<<<NN * DD / 4 / 256, 256>>>(x);
        small_gemm512<<<dim3(8, 8, 2), 256>>>(W_self, W_nb, W_comb);
        bias_kernel<<<512, 256>>>(b_self, b_nb, b_comb, W_comb);
        agg_gemm<<<dim3(4, 64), 256, AGG_SMEM>>>(adj);
        fin_gemm<<<dim3(4, 64), 256, FIN_SMEM>>>(out);
    }
}

// round 6
// speedup vs baseline: 1.3852x; 1.3852x over previous
#include <cuda_runtime.h>
#include <cuda_fp16.h>
#include <cstdint>

// GraphSAGE layer, N=8192, D_IN=D_OUT=512 — mma.sync fp16 (R4 structure) +
// two-stream fork-join overlap.
// out = relu( x @ (W_self@Wc_top) + agg @ (W_nb@Wc_bot) + c )
// agg = (mask @ x) * invdeg, mask = (adj > 0)  (mask EXACT in fp16)
// fp16 single-pass agg; final = (Yh+Yl) @ Wf with Y hi/lo fp16 split.

#define NN 8192
#define DD 512

// ------------------------------- device globals (no allocations allowed) ----
__device__ __align__(256) __half g_mask[(size_t)NN * NN];   // 128 MB, 0/1 fp16
__device__ __align__(256) __half g_xh[(size_t)NN * DD];     // x fp16 (agg B)
__device__ __align__(256) __half g_Yh[(size_t)NN * 1024];   // [x|agg] hi
__device__ __align__(256) __half g_Yl[(size_t)NN * 1024];   // [x|agg] lo
__device__ __align__(256) __half g_Wf[(size_t)1024 * DD];   // fused W fp16
__device__ float g_c[DD];
__device__ float g_invdeg[NN];

// ------------------------------------------------------------ PTX helpers ---
__device__ __forceinline__ uint32_t smem_u32(const void* p) {
    uint32_t a;
    asm("{ .reg .u64 t; cvta.to.shared.u64 t, %1; cvt.u32.u64 %0, t; }"
        : "=r"(a) : "l"(p));
    return a;
}
#define CP16(dst, src) \
    asm volatile("cp.async.cg.shared.global [%0], [%1], 16;" \
                 :: "r"(dst), "l"(src) : "memory")
#define CP_COMMIT() asm volatile("cp.async.commit_group;" ::: "memory")
#define CP_WAIT1() asm volatile("cp.async.wait_group 1;" ::: "memory")
#define CP_WAIT0() asm volatile("cp.async.wait_group 0;" ::: "memory")

__device__ __forceinline__ void ldsm4(uint32_t* r, uint32_t addr) {
    asm volatile("ldmatrix.sync.aligned.m8n8.x4.shared.b16 {%0,%1,%2,%3}, [%4];"
                 : "=r"(r[0]), "=r"(r[1]), "=r"(r[2]), "=r"(r[3]) : "r"(addr));
}
__device__ __forceinline__ void ldsm4t(uint32_t* r, uint32_t addr) {
    asm volatile("ldmatrix.sync.aligned.m8n8.x4.trans.shared.b16 {%0,%1,%2,%3}, [%4];"
                 : "=r"(r[0]), "=r"(r[1]), "=r"(r[2]), "=r"(r[3]) : "r"(addr));
}
__device__ __forceinline__ void mma_f16(float* d, const uint32_t* a,
                                        const uint32_t* b) {
    asm volatile(
        "mma.sync.aligned.m16n8k16.row.col.f32.f16.f16.f32 "
        "{%0,%1,%2,%3}, {%4,%5,%6,%7}, {%8,%9}, {%0,%1,%2,%3};"
        : "+f"(d[0]), "+f"(d[1]), "+f"(d[2]), "+f"(d[3])
        : "r"(a[0]), "r"(a[1]), "r"(a[2]), "r"(a[3]), "r"(b[0]), "r"(b[1]));
}

// -------------------------------------------- deg + mask fused (1 adj read) -
__global__ void deg_mask_kernel(const int* __restrict__ adj) {
    const int row = blockIdx.x;
    const int4* p = (const int4*)(adj + (size_t)row * NN);
    uint2* mout = (uint2*)(g_mask + (size_t)row * NN);
    int s = 0;
    for (int i = threadIdx.x; i < NN / 4; i += 256) {
        int4 v = p[i];
        unsigned m0 = (v.x > 0) ? 0x3C00u : 0u;   // fp16 1.0
        unsigned m1 = (v.y > 0) ? 0x3C00u : 0u;
        unsigned m2 = (v.z > 0) ? 0x3C00u : 0u;
        unsigned m3 = (v.w > 0) ? 0x3C00u : 0u;
        s += (v.x > 0) + (v.y > 0) + (v.z > 0) + (v.w > 0);
        mout[i] = make_uint2(m0 | (m1 << 16), m2 | (m3 << 16));
    }
    __shared__ int red[256];
    red[threadIdx.x] = s;
    __syncthreads();
    for (int o = 128; o > 0; o >>= 1) {
        if (threadIdx.x < o) red[threadIdx.x] += red[threadIdx.x + o];
        __syncthreads();
    }
    if (threadIdx.x == 0)
        g_invdeg[row] = 1.0f / fmaxf((float)red[0], 1.0f);
}

// ------------------- x -> xh (node-major) + Yh/Yl cols 0..511 ---------------
__global__ void conv_x_kernel(const float* __restrict__ x) {
    int idx = blockIdx.x * 256 + threadIdx.x;     // over N*D/4 float4
    float4 v = ((const float4*)x)[idx];
    float f[4] = {v.x, v.y, v.z, v.w};
    __half h[4], l[4];
#pragma unroll
    for (int j = 0; j < 4; j++) {
        h[j] = __float2half(f[j]);
        l[j] = __float2half(f[j] - __half2float(h[j]));
    }
    __half2 h01, h23, l01, l23;
    h01.x = h[0]; h01.y = h[1]; h23.x = h[2]; h23.y = h[3];
    l01.x = l[0]; l01.y = l[1]; l23.x = l[2]; l23.y = l[3];
    size_t o = (size_t)idx * 4;
    *(__half2*)&g_xh[o] = h01; *(__half2*)&g_xh[o + 2] = h23;
    int r = idx >> 7, c = (idx & 127) * 4;
    size_t oy = (size_t)r * 1024 + c;
    *(__half2*)&g_Yh[oy] = h01; *(__half2*)&g_Yh[oy + 2] = h23;
    *(__half2*)&g_Yl[oy] = l01; *(__half2*)&g_Yl[oy + 2] = l23;
}

// ---------- small 512^3 GEMMs (both halves, grid.z) -> Wf fp16 --------------
__global__ void small_gemm512(const float* __restrict__ W_self,
                              const float* __restrict__ W_nb,
                              const float* __restrict__ W_comb) {
    const int half = blockIdx.z;
    const float* A = half ? W_nb : W_self;
    const float* B = W_comb + (size_t)half * 512 * 512;
    __shared__ float As[16][68];
    __shared__ float Bs[16][64];
    const int t = threadIdx.x;
    const int bm = blockIdx.y * 64, bn = blockIdx.x * 64;
    const int ty = t >> 4, tx = t & 15;
    float acc[4][4] = {};
    for (int k0 = 0; k0 < 512; k0 += 16) {
        {
            int row = t >> 2, c4 = t & 3;
            float4 v = *(const float4*)(A + (size_t)(bm + row) * 512 + k0 + c4 * 4);
            As[c4 * 4 + 0][row] = v.x;
            As[c4 * 4 + 1][row] = v.y;
            As[c4 * 4 + 2][row] = v.z;
            As[c4 * 4 + 3][row] = v.w;
        }
        {
            int kr = t >> 4, c4 = t & 15;
            *(float4*)&Bs[kr][c4 * 4] =
                *(const float4*)(B + (size_t)(k0 + kr) * 512 + bn + c4 * 4);
        }
        __syncthreads();
#pragma unroll
        for (int k = 0; k < 16; k++) {
            float4 av = *(const float4*)&As[k][ty * 4];
            float4 bv = *(const float4*)&Bs[k][tx * 4];
            float a[4] = {av.x, av.y, av.z, av.w};
            float b[4] = {bv.x, bv.y, bv.z, bv.w};
#pragma unroll
            for (int i = 0; i < 4; i++)
#pragma unroll
                for (int j = 0; j < 4; j++) acc[i][j] += a[i] * b[j];
        }
        __syncthreads();
    }
#pragma unroll
    for (int i = 0; i < 4; i++)
#pragma unroll
        for (int j = 0; j < 4; j++) {
            int kk = half * 512 + bm + ty * 4 + i;   // K index of final GEMM
            int n = bn + tx * 4 + j;
            g_Wf[(size_t)kk * 512 + n] = __float2half(acc[i][j]);
        }
}

// ----------------------------------------------------------- fused bias -----
__global__ void bias_kernel(const float* __restrict__ b_self,
                            const float* __restrict__ b_nb,
                            const float* __restrict__ b_comb,
                            const float* __restrict__ Wc) {
    const int n = blockIdx.x;
    float s = 0.0f;
    for (int o = threadIdx.x; o < 1024; o += 256) {
        float b = (o < 512) ? b_self[o] : b_nb[o - 512];
        s += b * Wc[(size_t)o * 512 + n];
    }
    __shared__ float red[256];
    red[threadIdx.x] = s;
    __syncthreads();
    for (int o = 128; o > 0; o >>= 1) {
        if (threadIdx.x < o) red[threadIdx.x] += red[threadIdx.x + o];
        __syncthreads();
    }
    if (threadIdx.x == 0) g_c[n] = red[0] + b_comb[n];
}

// ------------------------------- big GEMMs: mma.sync fp16, cp.async x2buf ---
// BM=128, BN=128, BK=32; 8 warps (2m x 4n), warp tile 64x32.
// MODE 0 (agg):  A=mask, B=xh; epilogue *invdeg -> Yh/Yl cols 512..1023.
// MODE 1 (final):A={Yh,Yl}, B=Wf; D = (Yh+Yl)@Wf; epilogue +bias, relu.
#define SA_T (128 * 40)   // elems per A tile (rows padded to 40 = 80 B)
#define SB_T (32 * 136)   // elems per B tile (rows padded to 136 = 272 B)

template <int NA, int LDA, int LDB>
__device__ __forceinline__ void fill_tiles(
    uint32_t sb, int tid, int bm, int bn, int k0, int buf,
    const __half* const* Ap, const __half* Bpp) {
    constexpr int BOFF = 2 * NA * SA_T;
#pragma unroll
    for (int a = 0; a < NA; a++)
#pragma unroll
        for (int j = 0; j < 2; j++) {
            int idx = tid + j * 256;
            int row = idx >> 2, q = idx & 3;
            const __half* src = Ap[a] + (size_t)(bm + row) * LDA + k0 + q * 8;
            uint32_t dst = sb + ((buf * NA + a) * SA_T + row * 40 + q * 8) * 2;
            CP16(dst, src);
        }
#pragma unroll
    for (int j = 0; j < 2; j++) {
        int idx = tid + j * 256;
        int row = idx >> 4, q = idx & 15;
        const __half* src = Bpp + (size_t)(k0 + row) * LDB + bn + q * 8;
        uint32_t dst = sb + (BOFF + buf * SB_T + row * 136 + q * 8) * 2;
        CP16(dst, src);
    }
}

template <int MODE>
__global__ void __launch_bounds__(256, 2) mma_gemm(float* __restrict__ outp) {
    constexpr int K = (MODE == 0) ? 8192 : 1024;
    constexpr int NCH = K / 32;
    constexpr int NA = (MODE == 0) ? 1 : 2;
    constexpr int LDA = (MODE == 0) ? 8192 : 1024;
    constexpr int LDB = 512;
    constexpr int BOFF = 2 * NA * SA_T;

    extern __shared__ __half sm[];
    const uint32_t sb = smem_u32(sm);
    const int tid = threadIdx.x, lane = tid & 31, wid = tid >> 5;
    const int wm = wid & 1, wn = wid >> 1;
    const int bm = blockIdx.y * 128, bn = blockIdx.x * 128;

    const __half* Ap[2];
    const __half* Bp;
    if (MODE == 0) { Ap[0] = g_mask; Ap[1] = g_mask; Bp = g_xh; }
    else           { Ap[0] = g_Yh;   Ap[1] = g_Yl;   Bp = g_Wf; }

    float acc[4][4][4] = {};

    fill_tiles<NA, LDA, LDB>(sb, tid, bm, bn, 0, 0, Ap, Bp);
    CP_COMMIT();

    for (int c = 0; c < NCH; ++c) {
        const int buf = c & 1;
        if (c + 1 < NCH) {
            fill_tiles<NA, LDA, LDB>(sb, tid, bm, bn, (c + 1) * 32, buf ^ 1,
                                     Ap, Bp);
            CP_COMMIT();
            CP_WAIT1();
        } else {
            CP_WAIT0();
        }
        __syncthreads();

#pragma unroll
        for (int ks = 0; ks < 2; ks++) {
            uint32_t Af[NA][4][4];
            uint32_t Bf[4][2];
#pragma unroll
            for (int a = 0; a < NA; a++)
#pragma unroll
                for (int i = 0; i < 4; i++) {
                    int row = wm * 64 + i * 16 + (lane & 15);
                    int col = ks * 16 + ((lane >> 4) << 3);
                    ldsm4(Af[a][i],
                          sb + ((buf * NA + a) * SA_T + row * 40 + col) * 2);
                }
#pragma unroll
            for (int jp = 0; jp < 2; jp++) {
                int row = ks * 16 + (lane & 15);
                int col = wn * 32 + jp * 16 + ((lane >> 4) << 3);
                uint32_t r[4];
                ldsm4t(r, sb + (BOFF + buf * SB_T + row * 136 + col) * 2);
                Bf[jp * 2][0] = r[0];     Bf[jp * 2][1] = r[1];
                Bf[jp * 2 + 1][0] = r[2]; Bf[jp * 2 + 1][1] = r[3];
            }
#pragma unroll
            for (int a = 0; a < NA; a++)
#pragma unroll
                for (int i = 0; i < 4; i++)
#pragma unroll
                    for (int jn = 0; jn < 4; jn++)
                        mma_f16(acc[i][jn], Af[a][i], Bf[jn]);
        }
        __syncthreads();
    }

    // --------------------------------------------------------- epilogue ----
    const int gid = lane >> 2, tig = lane & 3;
#pragma unroll
    for (int i = 0; i < 4; i++)
#pragma unroll
        for (int h = 0; h < 2; h++) {
            const int gr = bm + wm * 64 + i * 16 + gid + h * 8;
            if (MODE == 0) {
                const float s = g_invdeg[gr];
#pragma unroll
                for (int jn = 0; jn < 4; jn++) {
                    int col = bn + wn * 32 + jn * 8 + tig * 2;
                    float v0 = acc[i][jn][h * 2 + 0] * s;
                    float v1 = acc[i][jn][h * 2 + 1] * s;
                    __half h0 = __float2half(v0);
                    __half h1 = __float2half(v1);
                    __half2 hp, lp;
                    hp.x = h0; hp.y = h1;
                    lp.x = __float2half(v0 - __half2float(h0));
                    lp.y = __float2half(v1 - __half2float(h1));
                    *(__half2*)&g_Yh[(size_t)gr * 1024 + 512 + col] = hp;
                    *(__half2*)&g_Yl[(size_t)gr * 1024 + 512 + col] = lp;
                }
            } else {
#pragma unroll
                for (int jn = 0; jn < 4; jn++) {
                    int col = bn + wn * 32 + jn * 8 + tig * 2;
                    float2 o;
                    o.x = fmaxf(acc[i][jn][h * 2 + 0] + g_c[col], 0.0f);
                    o.y = fmaxf(acc[i][jn][h * 2 + 1] + g_c[col + 1], 0.0f);
                    *(float2*)&outp[(size_t)gr * 512 + col] = o;
                }
            }
        }
}

// ---------------------------------------------------------------- launch ----
extern "C" void kernel_launch(void* const* d_in, const int* in_sizes, int n_in,
                              void* d_out, int out_size) {
    const float* x      = (const float*)d_in[0];
    const int*   adj    = (const int*)d_in[1];
    const float* W_self = (const float*)d_in[2];
    const float* b_self = (const float*)d_in[3];
    const float* W_nb   = (const float*)d_in[4];
    const float* b_nb   = (const float*)d_in[5];
    const float* W_comb = (const float*)d_in[6];
    const float* b_comb = (const float*)d_in[7];
    float* out = (float*)d_out;

    constexpr int SMEM0 = (2 * 1 * SA_T + 2 * SB_T) * 2;   // 37,888 B
    constexpr int SMEM1 = (2 * 2 * SA_T + 2 * SB_T) * 2;   // 58,368 B

    static cudaStream_t sW = 0, sX = 0;
    static cudaEvent_t evR = 0, evW = 0, evX = 0;
    static int inited = 0;
    if (!inited) {
        inited = 1;
        cudaFuncSetAttribute(mma_gemm<0>,
                             cudaFuncAttributeMaxDynamicSharedMemorySize, SMEM0);
        cudaFuncSetAttribute(mma_gemm<1>,
                             cudaFuncAttributeMaxDynamicSharedMemorySize, SMEM1);
        bool ok =
            cudaStreamCreateWithFlags(&sW, cudaStreamNonBlocking) == cudaSuccess &&
            cudaStreamCreateWithFlags(&sX, cudaStreamNonBlocking) == cudaSuccess &&
            cudaEventCreateWithFlags(&evR, cudaEventDisableTiming) == cudaSuccess &&
            cudaEventCreateWithFlags(&evW, cudaEventDisableTiming) == cudaSuccess &&
            cudaEventCreateWithFlags(&evX, cudaEventDisableTiming) == cudaSuccess;
        if (!ok) { sW = 0; sX = 0; }
    }

    if (sW) {
        // fork
        cudaEventRecord(evR, 0);
        cudaStreamWaitEvent(sW, evR, 0);
        cudaStreamWaitEvent(sX, evR, 0);
        // side stream W: weight fusion chain (joins before final GEMM)
        small_gemm512<<<dim3(8, 8, 2), 256, 0, sW>>>(W_self, W_nb, W_comb);
        bias_kernel<<<512, 256, 0, sW>>>(b_self, b_nb, b_comb, W_comb);
        cudaEventRecord(evW, sW);
        // side stream X: x conversion (joins before agg GEMM)
        conv_x_kernel<<<NN * DD / 4 / 256, 256, 0, sX>>>(x);
        cudaEventRecord(evX, sX);
        // main stream
        deg_mask_kernel<<<NN, 256>>>(adj);
        cudaStreamWaitEvent(0, evX, 0);
        mma_gemm<0><<<dim3(4, 64), 256, SMEM0>>>(nullptr);
        cudaStreamWaitEvent(0, evW, 0);
        mma_gemm<1><<<dim3(4, 64), 256, SMEM1>>>(out);
    } else {
        deg_mask_kernel<<<NN, 256>>>(adj);
        conv_x_kernel<<<NN * DD / 4 / 256, 256>>>(x);
        small_gemm512<<<dim3(8, 8, 2), 256>>>(W_self, W_nb, W_comb);
        bias_kernel<<<512, 256>>>(b_self, b_nb, b_comb, W_comb);
        mma_gemm<0><<<dim3(4, 64), 256, SMEM0>>>(nullptr);
        mma_gemm<1><<<dim3(4, 64), 256, SMEM1>>>(out);
    }
}